// round 15
// baseline (speedup 1.0000x reference)
#include <cuda_runtime.h>
#include <cuda_fp16.h>
#include <math.h>
#include <stdint.h>

#define N_NODES 50000
#define F_IN    512
#define H1D     500
#define H2D     100
#define NCLS    16
#define NB_SCAN 196     // ceil(50000/256)

// ---------------- device scratch (no allocations allowed) ----------------
__device__ __align__(16) float g_H[(size_t)N_NODES * 512];   // half: GEMM1/GEMM2 out
__device__ __align__(16) float g_A[(size_t)N_NODES * 512];   // half: spmm1 out, then h3 out
__device__ int   g_deg[N_NODES];
__device__ float g_dinv[N_NODES];
__device__ int   g_rowptr[N_NODES + 1];
__device__ int   g_cursor[N_NODES];
__device__ int   g_colidx[800000 + N_NODES];
__device__ float g_wnorm[800000 + N_NODES];
__device__ int   g_part[256];
__device__ int   g_poff[256];
__device__ int   g_is64;

// ---------------- graph preprocessing (R9, passing) ----------------

__global__ void detect_init_kernel(const long long* __restrict__ ei, int n) {
    if (blockIdx.x == 0) {
        __shared__ int bad;
        if (threadIdx.x == 0) bad = 0;
        __syncthreads();
        #pragma unroll
        for (int i = 0; i < 4; ++i) {
            long long v = ei[threadIdx.x * 4 + i];
            if (v < 0 || v >= (long long)N_NODES) bad = 1;
        }
        __syncthreads();
        if (threadIdx.x == 0) g_is64 = bad ? 0 : 1;
    } else {
        int i = (blockIdx.x - 1) * blockDim.x + threadIdx.x;
        if (i < n) g_deg[i] = 1;
    }
}

__global__ void hist_kernel(const void* __restrict__ ei, int E) {
    int e = blockIdx.x * blockDim.x + threadIdx.x;
    if (e >= E) return;
    int r = g_is64 ? (int)((const long long*)ei)[e] : ((const int*)ei)[e];
    atomicAdd(&g_deg[r], 1);
}

__global__ __launch_bounds__(256) void scan_p1_kernel(int n) {
    __shared__ int sm[256];
    int t = threadIdx.x;
    int i = blockIdx.x * 256 + t;
    sm[t] = (i < n) ? g_deg[i] : 0;
    __syncthreads();
    #pragma unroll
    for (int off = 128; off > 0; off >>= 1) {
        if (t < off) sm[t] += sm[t + off];
        __syncthreads();
    }
    if (t == 0) g_part[blockIdx.x] = sm[0];
}

__global__ __launch_bounds__(256) void scan_p2_kernel() {
    __shared__ int sm[256];
    int t = threadIdx.x;
    int v = (t < NB_SCAN) ? g_part[t] : 0;
    sm[t] = v;
    __syncthreads();
    #pragma unroll
    for (int off = 1; off < 256; off <<= 1) {
        int u = (t >= off) ? sm[t - off] : 0;
        __syncthreads();
        sm[t] += u;
        __syncthreads();
    }
    if (t < NB_SCAN) g_poff[t] = sm[t] - v;
}

__global__ __launch_bounds__(256) void scan_p3_kernel(int n) {
    __shared__ int sm[256];
    int t = threadIdx.x;
    int i = blockIdx.x * 256 + t;
    int d = (i < n) ? g_deg[i] : 0;
    sm[t] = d;
    __syncthreads();
    #pragma unroll
    for (int off = 1; off < 256; off <<= 1) {
        int u = (t >= off) ? sm[t - off] : 0;
        __syncthreads();
        sm[t] += u;
        __syncthreads();
    }
    int base = g_poff[blockIdx.x];
    if (i < n) {
        int excl = base + sm[t] - d;
        g_rowptr[i] = excl;
        g_cursor[i] = excl;
        g_dinv[i]   = rsqrtf((float)d);
        if (i == n - 1) g_rowptr[n] = excl + d;
    }
}

__global__ void fill_kernel(const void* __restrict__ ei, int E, int n) {
    int t = blockIdx.x * blockDim.x + threadIdx.x;
    if (t < E) {
        int r, c;
        if (g_is64) {
            r = (int)((const long long*)ei)[t];
            c = (int)((const long long*)ei)[E + t];
        } else {
            r = ((const int*)ei)[t];
            c = ((const int*)ei)[E + t];
        }
        int pos = atomicAdd(&g_cursor[r], 1);
        g_colidx[pos] = c;
        g_wnorm[pos]  = g_dinv[r] * g_dinv[c];
    } else if (t < E + n) {
        int i = t - E;
        int pos = atomicAdd(&g_cursor[i], 1);
        g_colidx[pos] = i;
        g_wnorm[pos]  = g_dinv[i] * g_dinv[i];
    }
}

// ---------------- FP16 mma.sync GEMM, ldmatrix fragments, BN=64 ------------

#define BM  128
#define BN  64
#define BK  16
#define ASTR2 12    // As row stride in half2; ldmatrix phase banks 3n%8 distinct
#define BSTR2 12    // Bs2n row stride in half2; same property

// C[m][n] = sum_k A[m][k]*B[k][n] + bias[n]; C -> g_H as __half2, pitch ldc2 half2
// a_id: 1 => A = g_A as half (lda in halves); 2 => A = Aext fp32 (lda in floats)
__global__ __launch_bounds__(256) void gemm_mma_kernel(
    const float* __restrict__ Aext, int a_id, int lda,
    const float* __restrict__ B, int ldb,
    const float* __restrict__ bias,
    int ldc2, int M, int Nn, int K)
{
    __shared__ __half2 As2[2][BM][ASTR2];    // cols 0..7 used (16 halves, m-major)
    __shared__ __half2 Bs2n[2][BN][BSTR2];   // row = n, cols 0..7 = k-pairs

    __shared__ float sbias[BN];

    const float*  Af = (a_id == 2) ? Aext : nullptr;
    const __half* Ah = (a_id == 1) ? (const __half*)g_A : nullptr;
    __half2* C2 = (__half2*)g_H;

    int tid = threadIdx.x, wid = tid >> 5, lane = tid & 31;
    int g = lane >> 2, tig = lane & 3;
    int wr = wid & 3, wc = wid >> 2;            // 4x2 warp grid, warp tile 32x32
    int m0 = blockIdx.y * BM, n0 = blockIdx.x * BN;

    if (tid < BN) {
        sbias[tid] = (n0 + tid < Nn) ? bias[n0 + tid] : 0.f;
    }

    float acc[2][4][4];
    #pragma unroll
    for (int i = 0; i < 2; i++)
        #pragma unroll
        for (int j = 0; j < 4; j++)
            #pragma unroll
            for (int q = 0; q < 4; q++) acc[i][j][q] = 0.f;

    int nIter = (K + BK - 1) >> 4;

    // B staging decomposition: e in [0,512): k-pair r = e&7, n col c = e>>3
    int sbr = tid & 7;          // k-pair row for this thread (p adds 256 -> same r)
    int sbc0 = tid >> 3;        // n col for p=0 (0..31); p=1 -> +32

    // preload chunk 0
    {
        int k0 = 0;
        #pragma unroll
        for (int p = 0; p < 2; ++p) {
            int f = p * 256 + tid;
            int r = f >> 2, c4 = f & 3;
            int gm = m0 + r;
            float v[4] = {0.f, 0.f, 0.f, 0.f};
            if (gm < M) {
                if (a_id == 2) {
                    if (k0 + 16 <= K) {
                        float4 t = *(const float4*)&Af[(size_t)gm * lda + k0 + c4 * 4];
                        v[0] = t.x; v[1] = t.y; v[2] = t.z; v[3] = t.w;
                    } else {
                        #pragma unroll
                        for (int e = 0; e < 4; ++e) {
                            int gk = k0 + c4 * 4 + e;
                            if (gk < K) v[e] = Af[(size_t)gm * lda + gk];
                        }
                    }
                } else {
                    if (k0 + 16 <= K) {
                        uint2 t = *(const uint2*)&Ah[(size_t)gm * lda + k0 + c4 * 4];
                        __half2 h0 = *(__half2*)&t.x, h1 = *(__half2*)&t.y;
                        float2 f0 = __half22float2(h0), f1 = __half22float2(h1);
                        v[0] = f0.x; v[1] = f0.y; v[2] = f1.x; v[3] = f1.y;
                    } else {
                        #pragma unroll
                        for (int e = 0; e < 4; ++e) {
                            int gk = k0 + c4 * 4 + e;
                            if (gk < K) v[e] = __half2float(Ah[(size_t)gm * lda + gk]);
                        }
                    }
                }
            }
            As2[0][r][2 * c4]     = __floats2half2_rn(v[0], v[1]);
            As2[0][r][2 * c4 + 1] = __floats2half2_rn(v[2], v[3]);
        }
        #pragma unroll
        for (int p = 0; p < 2; ++p) {
            int c = sbc0 + p * 32;
            int gk = k0 + 2 * sbr, gn = n0 + c;
            float v0 = (gk < K && gn < Nn) ? B[(size_t)gk * ldb + gn] : 0.f;
            float v1 = (gk + 1 < K && gn < Nn) ? B[(size_t)(gk + 1) * ldb + gn] : 0.f;
            Bs2n[0][c][sbr] = __floats2half2_rn(v0, v1);
        }
    }
    __syncthreads();

    int buf = 0;
    for (int it = 0; it < nIter; ++it) {
        bool hasNext = (it + 1) < nIter;
        int k1 = (it + 1) << 4;
        float ra[2][4];
        float rb[2][2];
        if (hasNext) {
            #pragma unroll
            for (int p = 0; p < 2; ++p) {
                int f = p * 256 + tid;
                int r = f >> 2, c4 = f & 3;
                int gm = m0 + r;
                ra[p][0] = ra[p][1] = ra[p][2] = ra[p][3] = 0.f;
                if (gm < M) {
                    if (a_id == 2) {
                        if (k1 + 16 <= K) {
                            float4 t = *(const float4*)&Af[(size_t)gm * lda + k1 + c4 * 4];
                            ra[p][0] = t.x; ra[p][1] = t.y; ra[p][2] = t.z; ra[p][3] = t.w;
                        } else {
                            #pragma unroll
                            for (int e = 0; e < 4; ++e) {
                                int gk = k1 + c4 * 4 + e;
                                if (gk < K) ra[p][e] = Af[(size_t)gm * lda + gk];
                            }
                        }
                    } else {
                        if (k1 + 16 <= K) {
                            uint2 t = *(const uint2*)&Ah[(size_t)gm * lda + k1 + c4 * 4];
                            __half2 h0 = *(__half2*)&t.x, h1 = *(__half2*)&t.y;
                            float2 f0 = __half22float2(h0), f1 = __half22float2(h1);
                            ra[p][0] = f0.x; ra[p][1] = f0.y; ra[p][2] = f1.x; ra[p][3] = f1.y;
                        } else {
                            #pragma unroll
                            for (int e = 0; e < 4; ++e) {
                                int gk = k1 + c4 * 4 + e;
                                if (gk < K) ra[p][e] = __half2float(Ah[(size_t)gm * lda + gk]);
                            }
                        }
                    }
                }
            }
            #pragma unroll
            for (int p = 0; p < 2; ++p) {
                int c = sbc0 + p * 32;
                int gk = k1 + 2 * sbr, gn = n0 + c;
                rb[p][0] = (gk < K && gn < Nn) ? B[(size_t)gk * ldb + gn] : 0.f;
                rb[p][1] = (gk + 1 < K && gn < Nn) ? B[(size_t)(gk + 1) * ldb + gn] : 0.f;
            }
        }

        // ---- fragment loads via ldmatrix, then 8 MMAs per warp ----
        {
            uint32_t af[2][4];
            #pragma unroll
            for (int i = 0; i < 2; ++i) {
                int rA = wr * 32 + i * 16 + (lane & 15);
                uint32_t addr = (uint32_t)__cvta_generic_to_shared(
                    &As2[buf][rA][(lane >> 4) * 4]);
                asm volatile(
                    "ldmatrix.sync.aligned.m8n8.x4.shared.b16 {%0,%1,%2,%3}, [%4];"
                    : "=r"(af[i][0]), "=r"(af[i][1]), "=r"(af[i][2]), "=r"(af[i][3])
                    : "r"(addr));
            }
            uint32_t bf[4][2];
            #pragma unroll
            for (int h = 0; h < 2; ++h) {
                int quad = lane >> 3, within = lane & 7;
                int row = wc * 32 + h * 16 + within + (quad >> 1) * 8;
                uint32_t addr = (uint32_t)__cvta_generic_to_shared(
                    &Bs2n[buf][row][(quad & 1) * 4]);
                asm volatile(
                    "ldmatrix.sync.aligned.m8n8.x4.shared.b16 {%0,%1,%2,%3}, [%4];"
                    : "=r"(bf[2 * h][0]), "=r"(bf[2 * h][1]),
                      "=r"(bf[2 * h + 1][0]), "=r"(bf[2 * h + 1][1])
                    : "r"(addr));
            }
            #pragma unroll
            for (int i = 0; i < 2; ++i)
                #pragma unroll
                for (int j = 0; j < 4; ++j) {
                    asm volatile(
                        "mma.sync.aligned.m16n8k16.row.col.f32.f16.f16.f32 "
                        "{%0,%1,%2,%3}, {%4,%5,%6,%7}, {%8,%9}, {%0,%1,%2,%3};"
                        : "+f"(acc[i][j][0]), "+f"(acc[i][j][1]),
                          "+f"(acc[i][j][2]), "+f"(acc[i][j][3])
                        : "r"(af[i][0]), "r"(af[i][1]), "r"(af[i][2]), "r"(af[i][3]),
                          "r"(bf[j][0]), "r"(bf[j][1]));
                }
        }

        if (hasNext) {
            int nb = buf ^ 1;
            #pragma unroll
            for (int p = 0; p < 2; ++p) {
                int f = p * 256 + tid;
                int r = f >> 2, c4 = f & 3;
                As2[nb][r][2 * c4]     = __floats2half2_rn(ra[p][0], ra[p][1]);
                As2[nb][r][2 * c4 + 1] = __floats2half2_rn(ra[p][2], ra[p][3]);
            }
            #pragma unroll
            for (int p = 0; p < 2; ++p) {
                int c = sbc0 + p * 32;
                Bs2n[nb][c][sbr] = __floats2half2_rn(rb[p][0], rb[p][1]);
            }
        }
        __syncthreads();
        buf ^= 1;
    }

    // ---- epilogue: bias add, half2 stores ----
    #pragma unroll
    for (int i = 0; i < 2; ++i) {
        int r0 = m0 + wr * 32 + i * 16 + g;
        int r1 = r0 + 8;
        #pragma unroll
        for (int j = 0; j < 4; ++j) {
            int nn = n0 + wc * 32 + j * 8 + 2 * tig;
            if (nn < Nn) {
                float b0 = sbias[wc * 32 + j * 8 + 2 * tig];
                float b1 = sbias[wc * 32 + j * 8 + 2 * tig + 1];
                if (r0 < M)
                    C2[(size_t)r0 * ldc2 + (nn >> 1)] =
                        __floats2half2_rn(acc[i][j][0] + b0, acc[i][j][1] + b1);
                if (r1 < M)
                    C2[(size_t)r1 * ldc2 + (nn >> 1)] =
                        __floats2half2_rn(acc[i][j][2] + b0, acc[i][j][3] + b1);
            }
        }
    }
}

// ---------------- SpMM1: 2 warps/row + tanh, half out (R9, passing) --------

__global__ __launch_bounds__(256) void spmm1_tanh_h_kernel(int n)
{
    const uint4* Hh = (const uint4*)g_H;       // 8 halves per uint4, pitch 64
    uint4* Out4 = (uint4*)g_A;                 // pitch 64 uint4 (512 halves)

    int gw = (blockIdx.x * blockDim.x + threadIdx.x) >> 5;
    int row = gw >> 1, half = gw & 1;
    if (row >= n) return;
    int lane = threadIdx.x & 31;
    int idx = half * 32 + lane;
    bool valid = idx < 63;

    float2 acc[4];
    #pragma unroll
    for (int p = 0; p < 4; ++p) acc[p] = make_float2(0.f, 0.f);

    int s = g_rowptr[row], e = g_rowptr[row + 1];
    for (int j = s; j < e; ++j) {
        int   c  = __ldg(&g_colidx[j]);
        float wj = __ldg(&g_wnorm[j]);
        if (valid) {
            uint4 v = Hh[(size_t)c * 64 + idx];
            #pragma unroll
            for (int p = 0; p < 4; ++p) {
                float2 f = __half22float2(*(const __half2*)((&v.x) + p));
                acc[p].x += wj * f.x;
                acc[p].y += wj * f.y;
            }
        }
    }
    if (valid) {
        __half2 h0 = __floats2half2_rn(tanhf(acc[0].x), tanhf(acc[0].y));
        __half2 h1 = __floats2half2_rn(tanhf(acc[1].x), tanhf(acc[1].y));
        __half2 h2 = __floats2half2_rn(tanhf(acc[2].x), tanhf(acc[2].y));
        __half2 h3 = __floats2half2_rn(tanhf(acc[3].x), tanhf(acc[3].y));
        uint4 o;
        o.x = *(uint32_t*)&h0; o.y = *(uint32_t*)&h1;
        o.z = *(uint32_t*)&h2; o.w = *(uint32_t*)&h3;
        Out4[(size_t)row * 64 + idx] = o;
    }
}

// ---------------- fused: SpMM2 + tanh + gemm3 -> h3 (R9, passing) ----------

__global__ __launch_bounds__(256) void spmm2_gemm3_kernel(
    const float* __restrict__ W3, const float* __restrict__ b3, int n)
{
    __shared__ float st[8][104];
    __shared__ float W3s[H2D * NCLS];
    __shared__ float b3s[NCLS];

    int tid = threadIdx.x;
    for (int i = tid; i < H2D * NCLS; i += 256) W3s[i] = W3[i];
    if (tid < NCLS) b3s[tid] = b3[tid];

    int w = tid >> 5, lane = tid & 31;
    int row = blockIdx.x * 8 + w;
    const __half2* Hh = (const __half2*)g_H;   // pitch 64 half2 (128 halves)

    if (row < n) {
        float2 acc0 = make_float2(0.f, 0.f);
        float2 acc1 = make_float2(0.f, 0.f);
        int s = g_rowptr[row], e = g_rowptr[row + 1];
        for (int j = s; j < e; ++j) {
            int   c  = __ldg(&g_colidx[j]);
            float wj = __ldg(&g_wnorm[j]);
            const __half2* base = Hh + (size_t)c * 64;
            {
                float2 f = __half22float2(base[lane]);
                acc0.x += wj * f.x; acc0.y += wj * f.y;
            }
            if (lane < 18) {
                float2 f = __half22float2(base[lane + 32]);
                acc1.x += wj * f.x; acc1.y += wj * f.y;
            }
        }
        *(float2*)&st[w][2 * lane] = make_float2(tanhf(acc0.x), tanhf(acc0.y));
        if (lane < 18)
            *(float2*)&st[w][64 + 2 * lane] = make_float2(tanhf(acc1.x), tanhf(acc1.y));
    }
    __syncthreads();

    if (tid < 128) {
        int r = tid >> 4, c = tid & 15;
        int grow = blockIdx.x * 8 + r;
        if (grow < n) {
            float a = b3s[c];
            #pragma unroll 4
            for (int k = 0; k < H2D; ++k) a += st[r][k] * W3s[k * NCLS + c];
            ((__half*)g_A)[(size_t)grow * NCLS + c] = __float2half(a);
        }
    }
}

// ---------------- spmm3 (half gather) + tanh + softmax (R9, passing) -------

__global__ __launch_bounds__(256) void spmm3_softmax_kernel(float* __restrict__ out, int n)
{
    int row = blockIdx.x * blockDim.x + threadIdx.x;
    if (row >= n) return;
    const uint4* Hh = (const uint4*)g_A;

    float acc[NCLS];
    #pragma unroll
    for (int j = 0; j < NCLS; j++) acc[j] = 0.f;

    int s = g_rowptr[row], e = g_rowptr[row + 1];
    for (int j = s; j < e; ++j) {
        int   c  = __ldg(&g_colidx[j]);
        float wj = __ldg(&g_wnorm[j]);
        uint4 v0 = Hh[(size_t)c * 2];
        uint4 v1 = Hh[(size_t)c * 2 + 1];
        #pragma unroll
        for (int q = 0; q < 4; ++q) {
            float2 f = __half22float2(*(const __half2*)((&v0.x) + q));
            acc[2 * q] += wj * f.x; acc[2 * q + 1] += wj * f.y;
        }
        #pragma unroll
        for (int q = 0; q < 4; ++q) {
            float2 f = __half22float2(*(const __half2*)((&v1.x) + q));
            acc[8 + 2 * q] += wj * f.x; acc[8 + 2 * q + 1] += wj * f.y;
        }
    }
    float mx = -1e30f;
    #pragma unroll
    for (int j = 0; j < NCLS; j++) { acc[j] = tanhf(acc[j]); mx = fmaxf(mx, acc[j]); }
    float sum = 0.f;
    #pragma unroll
    for (int j = 0; j < NCLS; j++) { acc[j] = expf(acc[j] - mx); sum += acc[j]; }
    float inv = 1.f / sum;
    float* o = out + (size_t)row * NCLS;
    #pragma unroll
    for (int j = 0; j < NCLS; j++) o[j] = acc[j] * inv;
}

// ---------------- launch ----------------

extern "C" void kernel_launch(void* const* d_in, const int* in_sizes, int n_in,
                              void* d_out, int out_size)
{
    const float* x  = (const float*)d_in[0];
    const void*  ei = d_in[1];
    const float* W1 = (const float*)d_in[2];
    const float* b1 = (const float*)d_in[3];
    const float* W2 = (const float*)d_in[4];
    const float* b2 = (const float*)d_in[5];
    const float* W3 = (const float*)d_in[6];
    const float* b3 = (const float*)d_in[7];
    float* out = (float*)d_out;

    int n = in_sizes[0] / F_IN;   // 50000
    int E = in_sizes[1] / 2;      // 800000

    cudaStream_t s2;
    cudaStreamCreateWithFlags(&s2, cudaStreamNonBlocking);
    cudaEvent_t evFork, evJoin;
    cudaEventCreateWithFlags(&evFork, cudaEventDisableTiming);
    cudaEventCreateWithFlags(&evJoin, cudaEventDisableTiming);

    cudaEventRecord(evFork, 0);
    cudaStreamWaitEvent(s2, evFork, 0);

    // enqueue order keeps gemm1 at launch index 3 (ncu -s 5 -c 1 lands there)
    detect_init_kernel<<<1 + (n + 255) / 256, 256, 0, s2>>>((const long long*)ei, n); // 0
    hist_kernel<<<(E + 255) / 256, 256, 0, s2>>>(ei, E);                              // 1
    scan_p1_kernel<<<NB_SCAN, 256, 0, s2>>>(n);                                       // 2
    {   // layer-1 GEMM: x (fp32, a_id=2) x W1 -> g_H half (pitch 256 half2)          // 3 (main)
        dim3 g((H1D + BN - 1) / BN, (n + BM - 1) / BM);
        gemm_mma_kernel<<<g, 256>>>(x, 2, F_IN, W1, H1D, b1, 256, n, H1D, F_IN);
    }
    scan_p2_kernel<<<1, 256, 0, s2>>>();                                              // 4
    scan_p3_kernel<<<NB_SCAN, 256, 0, s2>>>(n);                                       // 5
    fill_kernel<<<(E + n + 255) / 256, 256, 0, s2>>>(ei, E, n);                       // 6
    cudaEventRecord(evJoin, s2);

    // join: SpMM1 needs both CSR and GEMM1
    cudaStreamWaitEvent(0, evJoin, 0);
    spmm1_tanh_h_kernel<<<(n * 64 + 255) / 256, 256>>>(n);

    // layer-2 GEMM: g_A (half, a_id=1) x W2, K=500 guarded -> g_H half (pitch 64 half2)
    {
        dim3 g((H2D + BN - 1) / BN, (n + BM - 1) / BM);
        gemm_mma_kernel<<<g, 256>>>(nullptr, 1, 512, W2, H2D, b2, 64, n, H2D, H1D);
    }

    // fused SpMM2 + tanh + gemm3 -> g_A half (pitch 16), then spmm3+softmax
    spmm2_gemm3_kernel<<<(n + 7) / 8, 256>>>(W3, b3, n);
    spmm3_softmax_kernel<<<(n + 255) / 256, 256>>>(out, n);

    cudaEventDestroy(evFork);
    cudaEventDestroy(evJoin);
    cudaStreamDestroy(s2);
}

// round 16
// speedup vs baseline: 1.0786x; 1.0786x over previous
#include <cuda_runtime.h>
#include <cuda_fp16.h>
#include <math.h>
#include <stdint.h>

#define N_NODES 50000
#define F_IN    512
#define H1D     500
#define H2D     100
#define NCLS    16
#define NB_SCAN 196     // ceil(50000/256)

// ---------------- device scratch (no allocations allowed) ----------------
__device__ __align__(16) float g_H[(size_t)N_NODES * 512];   // half: GEMM1/GEMM2 out
__device__ __align__(16) float g_A[(size_t)N_NODES * 512];   // half: spmm1 out, then h3 out
__device__ __align__(16) __half2 g_X[(size_t)N_NODES * 256]; // x as half (R13-proven)
__device__ __align__(16) __half2 g_Wt1[256 * 512];           // W1 k-pair interleaved, padded
__device__ __align__(16) __half2 g_Wt2[256 * 512];           // W2 k-pair interleaved, padded
__device__ int   g_deg[N_NODES];
__device__ float g_dinv[N_NODES];
__device__ int   g_rowptr[N_NODES + 1];
__device__ int   g_cursor[N_NODES];
__device__ int   g_colidx[800000 + N_NODES];
__device__ float g_wnorm[800000 + N_NODES];
__device__ int   g_part[256];
__device__ int   g_poff[256];
__device__ int   g_is64;

// ---------------- graph preprocessing (passing since R8) ----------------

__global__ void detect_init_kernel(const long long* __restrict__ ei, int n) {
    if (blockIdx.x == 0) {
        __shared__ int bad;
        if (threadIdx.x == 0) bad = 0;
        __syncthreads();
        #pragma unroll
        for (int i = 0; i < 4; ++i) {
            long long v = ei[threadIdx.x * 4 + i];
            if (v < 0 || v >= (long long)N_NODES) bad = 1;
        }
        __syncthreads();
        if (threadIdx.x == 0) g_is64 = bad ? 0 : 1;
    } else {
        int i = (blockIdx.x - 1) * blockDim.x + threadIdx.x;
        if (i < n) g_deg[i] = 1;
    }
}

__global__ void hist_kernel(const void* __restrict__ ei, int E) {
    int e = blockIdx.x * blockDim.x + threadIdx.x;
    if (e >= E) return;
    int r = g_is64 ? (int)((const long long*)ei)[e] : ((const int*)ei)[e];
    atomicAdd(&g_deg[r], 1);
}

__global__ __launch_bounds__(256) void scan_p1_kernel(int n) {
    __shared__ int sm[256];
    int t = threadIdx.x;
    int i = blockIdx.x * 256 + t;
    sm[t] = (i < n) ? g_deg[i] : 0;
    __syncthreads();
    #pragma unroll
    for (int off = 128; off > 0; off >>= 1) {
        if (t < off) sm[t] += sm[t + off];
        __syncthreads();
    }
    if (t == 0) g_part[blockIdx.x] = sm[0];
}

__global__ __launch_bounds__(256) void scan_p2_kernel() {
    __shared__ int sm[256];
    int t = threadIdx.x;
    int v = (t < NB_SCAN) ? g_part[t] : 0;
    sm[t] = v;
    __syncthreads();
    #pragma unroll
    for (int off = 1; off < 256; off <<= 1) {
        int u = (t >= off) ? sm[t - off] : 0;
        __syncthreads();
        sm[t] += u;
        __syncthreads();
    }
    if (t < NB_SCAN) g_poff[t] = sm[t] - v;
}

__global__ __launch_bounds__(256) void scan_p3_kernel(int n) {
    __shared__ int sm[256];
    int t = threadIdx.x;
    int i = blockIdx.x * 256 + t;
    int d = (i < n) ? g_deg[i] : 0;
    sm[t] = d;
    __syncthreads();
    #pragma unroll
    for (int off = 1; off < 256; off <<= 1) {
        int u = (t >= off) ? sm[t - off] : 0;
        __syncthreads();
        sm[t] += u;
        __syncthreads();
    }
    int base = g_poff[blockIdx.x];
    if (i < n) {
        int excl = base + sm[t] - d;
        g_rowptr[i] = excl;
        g_cursor[i] = excl;
        g_dinv[i]   = rsqrtf((float)d);
        if (i == n - 1) g_rowptr[n] = excl + d;
    }
}

__global__ void fill_kernel(const void* __restrict__ ei, int E, int n) {
    int t = blockIdx.x * blockDim.x + threadIdx.x;
    if (t < E) {
        int r, c;
        if (g_is64) {
            r = (int)((const long long*)ei)[t];
            c = (int)((const long long*)ei)[E + t];
        } else {
            r = ((const int*)ei)[t];
            c = ((const int*)ei)[E + t];
        }
        int pos = atomicAdd(&g_cursor[r], 1);
        g_colidx[pos] = c;
        g_wnorm[pos]  = g_dinv[r] * g_dinv[c];
    } else if (t < E + n) {
        int i = t - E;
        int pos = atomicAdd(&g_cursor[i], 1);
        g_colidx[pos] = i;
        g_wnorm[pos]  = g_dinv[i] * g_dinv[i];
    }
}

// ---------------- input conversion to half ----------------

__global__ __launch_bounds__(256) void conv_x_kernel(const float* __restrict__ x, int n) {
    int idx = blockIdx.x * 256 + threadIdx.x;
    if (idx >= n * 256) return;
    int row = idx >> 8, c2 = idx & 255;
    float2 f = *(const float2*)&x[(size_t)row * 512 + c2 * 2];
    g_X[idx] = __floats2half2_rn(f.x, f.y);
}

// W1 [512,500] & W2 [500,100] fp32 -> k-pair interleaved [256][512] half2, zero-padded
__global__ __launch_bounds__(256) void conv_w_kernel(
    const float* __restrict__ W1, const float* __restrict__ W2)
{
    int idx = blockIdx.x * 256 + threadIdx.x;
    if (idx < 256 * 512) {
        int k2 = idx >> 9, nn = idx & 511;
        float v0 = (nn < H1D) ? W1[(size_t)(2 * k2) * H1D + nn] : 0.f;
        float v1 = (nn < H1D) ? W1[(size_t)(2 * k2 + 1) * H1D + nn] : 0.f;
        g_Wt1[idx] = __floats2half2_rn(v0, v1);
    } else {
        int j = idx - 256 * 512;
        int k2 = j >> 9, nn = j & 511;
        float v0 = (2 * k2 < H1D && nn < H2D) ? W2[(size_t)(2 * k2) * H2D + nn] : 0.f;
        float v1 = (2 * k2 + 1 < H1D && nn < H2D) ? W2[(size_t)(2 * k2 + 1) * H2D + nn] : 0.f;
        g_Wt2[j] = __floats2half2_rn(v0, v1);
    }
}

// ---------------- FP16 mma.sync GEMM (R14 structure), raw-half staging ------

#define BM  128
#define BN  64
#define BK  16
#define ASTR2 12    // As row stride in half2: frag addr 12g+tig distinct mod 32
#define BSTR2 72    // Bs row stride in half2: frag addr 8*tig+g distinct mod 32

// C[m][n] = sum_k A[m][k]*B[k][n] + bias[n]; C -> g_H as __half2, pitch ldc2 half2
// a_id: 1 => A = g_A half; 3 => A = g_X half; 2 => A = Aext fp32
// b_id: 1 => B = g_Wt1 half2 (padded); 2 => g_Wt2; 0 => Bext fp32
__global__ __launch_bounds__(256) void gemm_mma_kernel(
    const float* __restrict__ Aext, int a_id, int lda,
    int b_id, const float* __restrict__ Bext, int ldb,
    const float* __restrict__ bias,
    int ldc2, int M, int Nn, int K)
{
    __shared__ __half2 As2[2][BM][ASTR2];
    __shared__ __half2 Bs2[2][BK / 2][BSTR2];
    __shared__ float sbias[BN];

    const float*  Af = (a_id == 2) ? Aext : nullptr;
    const __half* Ah = (a_id == 1) ? (const __half*)g_A
                     : (a_id == 3) ? (const __half*)g_X : nullptr;
    const __half2* Bt = (b_id == 1) ? g_Wt1 : (b_id == 2) ? g_Wt2 : nullptr;
    __half2* C2 = (__half2*)g_H;

    int tid = threadIdx.x, wid = tid >> 5, lane = tid & 31;
    int g = lane >> 2, tig = lane & 3;
    int wr = wid & 3, wc = wid >> 2;            // 4x2 warp grid, warp tile 32x32
    int m0 = blockIdx.y * BM, n0 = blockIdx.x * BN;

    if (tid < BN) {
        sbias[tid] = (n0 + tid < Nn) ? bias[n0 + tid] : 0.f;
    }

    float acc[2][4][4];
    #pragma unroll
    for (int i = 0; i < 2; i++)
        #pragma unroll
        for (int j = 0; j < 4; j++)
            #pragma unroll
            for (int q = 0; q < 4; q++) acc[i][j][q] = 0.f;

    int nIter = (K + BK - 1) >> 4;

    // preload chunk 0
    {
        int k0 = 0;
        #pragma unroll
        for (int p = 0; p < 2; ++p) {
            int f = p * 256 + tid;
            int r = f >> 2, c4 = f & 3;
            int gm = m0 + r;
            uint2 av = make_uint2(0u, 0u);
            if (gm < M) {
                if (a_id == 2) {
                    float v[4] = {0.f, 0.f, 0.f, 0.f};
                    if (k0 + 16 <= K) {
                        float4 t = *(const float4*)&Af[(size_t)gm * lda + k0 + c4 * 4];
                        v[0] = t.x; v[1] = t.y; v[2] = t.z; v[3] = t.w;
                    } else {
                        #pragma unroll
                        for (int e = 0; e < 4; ++e) {
                            int gk = k0 + c4 * 4 + e;
                            if (gk < K) v[e] = Af[(size_t)gm * lda + gk];
                        }
                    }
                    __half2 h0 = __floats2half2_rn(v[0], v[1]);
                    __half2 h1 = __floats2half2_rn(v[2], v[3]);
                    av.x = *(uint32_t*)&h0; av.y = *(uint32_t*)&h1;
                } else {
                    // raw half copy; k beyond K is covered by zero-padded Wt
                    av = *(const uint2*)&Ah[(size_t)gm * lda + k0 + c4 * 4];
                }
            }
            As2[0][r][2 * c4]     = *(__half2*)&av.x;
            As2[0][r][2 * c4 + 1] = *(__half2*)&av.y;
        }
        #pragma unroll
        for (int p = 0; p < 2; ++p) {
            int e = p * 256 + tid;
            int r = e >> 6, c = e & 63;
            if (b_id != 0) {
                Bs2[0][r][c] = Bt[(size_t)((k0 >> 1) + r) * 512 + n0 + c];
            } else {
                int gk = k0 + 2 * r, gn = n0 + c;
                float v0 = (gk < K && gn < Nn) ? Bext[(size_t)gk * ldb + gn] : 0.f;
                float v1 = (gk + 1 < K && gn < Nn) ? Bext[(size_t)(gk + 1) * ldb + gn] : 0.f;
                Bs2[0][r][c] = __floats2half2_rn(v0, v1);
            }
        }
    }
    __syncthreads();

    int buf = 0;
    for (int it = 0; it < nIter; ++it) {
        bool hasNext = (it + 1) < nIter;
        int k1 = (it + 1) << 4;
        uint2 ra2[2];
        __half2 rb2[2];
        if (hasNext) {
            #pragma unroll
            for (int p = 0; p < 2; ++p) {
                int f = p * 256 + tid;
                int r = f >> 2, c4 = f & 3;
                int gm = m0 + r;
                ra2[p] = make_uint2(0u, 0u);
                if (gm < M) {
                    if (a_id == 2) {
                        float v[4] = {0.f, 0.f, 0.f, 0.f};
                        if (k1 + 16 <= K) {
                            float4 t = *(const float4*)&Af[(size_t)gm * lda + k1 + c4 * 4];
                            v[0] = t.x; v[1] = t.y; v[2] = t.z; v[3] = t.w;
                        } else {
                            #pragma unroll
                            for (int e = 0; e < 4; ++e) {
                                int gk = k1 + c4 * 4 + e;
                                if (gk < K) v[e] = Af[(size_t)gm * lda + gk];
                            }
                        }
                        __half2 h0 = __floats2half2_rn(v[0], v[1]);
                        __half2 h1 = __floats2half2_rn(v[2], v[3]);
                        ra2[p].x = *(uint32_t*)&h0; ra2[p].y = *(uint32_t*)&h1;
                    } else {
                        ra2[p] = *(const uint2*)&Ah[(size_t)gm * lda + k1 + c4 * 4];
                    }
                }
            }
            #pragma unroll
            for (int p = 0; p < 2; ++p) {
                int e = p * 256 + tid;
                int r = e >> 6, c = e & 63;
                if (b_id != 0) {
                    rb2[p] = Bt[(size_t)((k1 >> 1) + r) * 512 + n0 + c];
                } else {
                    int gk = k1 + 2 * r, gn = n0 + c;
                    float v0 = (gk < K && gn < Nn) ? Bext[(size_t)gk * ldb + gn] : 0.f;
                    float v1 = (gk + 1 < K && gn < Nn) ? Bext[(size_t)(gk + 1) * ldb + gn] : 0.f;
                    rb2[p] = __floats2half2_rn(v0, v1);
                }
            }
        }

        // ---- one m16n8k16 MMA sweep over the BK=16 chunk (8 MMAs/warp) ----
        {
            uint32_t af[2][4];
            #pragma unroll
            for (int i = 0; i < 2; ++i) {
                int rA = wr * 32 + i * 16;
                af[i][0] = *(const uint32_t*)&As2[buf][rA + g    ][tig    ];
                af[i][1] = *(const uint32_t*)&As2[buf][rA + g + 8][tig    ];
                af[i][2] = *(const uint32_t*)&As2[buf][rA + g    ][tig + 4];
                af[i][3] = *(const uint32_t*)&As2[buf][rA + g + 8][tig + 4];
            }
            uint32_t bf[4][2];
            #pragma unroll
            for (int j = 0; j < 4; ++j) {
                int cB = wc * 32 + j * 8 + g;
                bf[j][0] = *(const uint32_t*)&Bs2[buf][tig    ][cB];
                bf[j][1] = *(const uint32_t*)&Bs2[buf][tig + 4][cB];
            }
            #pragma unroll
            for (int i = 0; i < 2; ++i)
                #pragma unroll
                for (int j = 0; j < 4; ++j) {
                    asm volatile(
                        "mma.sync.aligned.m16n8k16.row.col.f32.f16.f16.f32 "
                        "{%0,%1,%2,%3}, {%4,%5,%6,%7}, {%8,%9}, {%0,%1,%2,%3};"
                        : "+f"(acc[i][j][0]), "+f"(acc[i][j][1]),
                          "+f"(acc[i][j][2]), "+f"(acc[i][j][3])
                        : "r"(af[i][0]), "r"(af[i][1]), "r"(af[i][2]), "r"(af[i][3]),
                          "r"(bf[j][0]), "r"(bf[j][1]));
                }
        }

        if (hasNext) {
            int nb = buf ^ 1;
            #pragma unroll
            for (int p = 0; p < 2; ++p) {
                int f = p * 256 + tid;
                int r = f >> 2, c4 = f & 3;
                As2[nb][r][2 * c4]     = *(__half2*)&ra2[p].x;
                As2[nb][r][2 * c4 + 1] = *(__half2*)&ra2[p].y;
            }
            #pragma unroll
            for (int p = 0; p < 2; ++p) {
                int e = p * 256 + tid;
                int r = e >> 6, c = e & 63;
                Bs2[nb][r][c] = rb2[p];
            }
        }
        __syncthreads();
        buf ^= 1;
    }

    // ---- epilogue: bias add, half2 stores ----
    #pragma unroll
    for (int i = 0; i < 2; ++i) {
        int r0 = m0 + wr * 32 + i * 16 + g;
        int r1 = r0 + 8;
        #pragma unroll
        for (int j = 0; j < 4; ++j) {
            int nn = n0 + wc * 32 + j * 8 + 2 * tig;
            if (nn < Nn) {
                float b0 = sbias[wc * 32 + j * 8 + 2 * tig];
                float b1 = sbias[wc * 32 + j * 8 + 2 * tig + 1];
                if (r0 < M)
                    C2[(size_t)r0 * ldc2 + (nn >> 1)] =
                        __floats2half2_rn(acc[i][j][0] + b0, acc[i][j][1] + b1);
                if (r1 < M)
                    C2[(size_t)r1 * ldc2 + (nn >> 1)] =
                        __floats2half2_rn(acc[i][j][2] + b0, acc[i][j][3] + b1);
            }
        }
    }
}

// ---------------- SpMM1: 2 warps/row + tanh, half out (R9, passing) --------

__global__ __launch_bounds__(256) void spmm1_tanh_h_kernel(int n)
{
    const uint4* Hh = (const uint4*)g_H;       // 8 halves per uint4, pitch 64
    uint4* Out4 = (uint4*)g_A;                 // pitch 64 uint4 (512 halves)

    int gw = (blockIdx.x * blockDim.x + threadIdx.x) >> 5;
    int row = gw >> 1, half = gw & 1;
    if (row >= n) return;
    int lane = threadIdx.x & 31;
    int idx = half * 32 + lane;
    bool valid = idx < 63;

    float2 acc[4];
    #pragma unroll
    for (int p = 0; p < 4; ++p) acc[p] = make_float2(0.f, 0.f);

    int s = g_rowptr[row], e = g_rowptr[row + 1];
    for (int j = s; j < e; ++j) {
        int   c  = __ldg(&g_colidx[j]);
        float wj = __ldg(&g_wnorm[j]);
        if (valid) {
            uint4 v = Hh[(size_t)c * 64 + idx];
            #pragma unroll
            for (int p = 0; p < 4; ++p) {
                float2 f = __half22float2(*(const __half2*)((&v.x) + p));
                acc[p].x += wj * f.x;
                acc[p].y += wj * f.y;
            }
        }
    }
    if (valid) {
        __half2 h0 = __floats2half2_rn(tanhf(acc[0].x), tanhf(acc[0].y));
        __half2 h1 = __floats2half2_rn(tanhf(acc[1].x), tanhf(acc[1].y));
        __half2 h2 = __floats2half2_rn(tanhf(acc[2].x), tanhf(acc[2].y));
        __half2 h3 = __floats2half2_rn(tanhf(acc[3].x), tanhf(acc[3].y));
        uint4 o;
        o.x = *(uint32_t*)&h0; o.y = *(uint32_t*)&h1;
        o.z = *(uint32_t*)&h2; o.w = *(uint32_t*)&h3;
        Out4[(size_t)row * 64 + idx] = o;
    }
}

// ---------------- fused: SpMM2 + tanh + gemm3 -> h3 (R9, passing) ----------

__global__ __launch_bounds__(256) void spmm2_gemm3_kernel(
    const float* __restrict__ W3, const float* __restrict__ b3, int n)
{
    __shared__ float st[8][104];
    __shared__ float W3s[H2D * NCLS];
    __shared__ float b3s[NCLS];

    int tid = threadIdx.x;
    for (int i = tid; i < H2D * NCLS; i += 256) W3s[i] = W3[i];
    if (tid < NCLS) b3s[tid] = b3[tid];

    int w = tid >> 5, lane = tid & 31;
    int row = blockIdx.x * 8 + w;
    const __half2* Hh = (const __half2*)g_H;   // pitch 64 half2 (128 halves)

    if (row < n) {
        float2 acc0 = make_float2(0.f, 0.f);
        float2 acc1 = make_float2(0.f, 0.f);
        int s = g_rowptr[row], e = g_rowptr[row + 1];
        for (int j = s; j < e; ++j) {
            int   c  = __ldg(&g_colidx[j]);
            float wj = __ldg(&g_wnorm[j]);
            const __half2* base = Hh + (size_t)c * 64;
            {
                float2 f = __half22float2(base[lane]);
                acc0.x += wj * f.x; acc0.y += wj * f.y;
            }
            if (lane < 18) {
                float2 f = __half22float2(base[lane + 32]);
                acc1.x += wj * f.x; acc1.y += wj * f.y;
            }
        }
        *(float2*)&st[w][2 * lane] = make_float2(tanhf(acc0.x), tanhf(acc0.y));
        if (lane < 18)
            *(float2*)&st[w][64 + 2 * lane] = make_float2(tanhf(acc1.x), tanhf(acc1.y));
    }
    __syncthreads();

    if (tid < 128) {
        int r = tid >> 4, c = tid & 15;
        int grow = blockIdx.x * 8 + r;
        if (grow < n) {
            float a = b3s[c];
            #pragma unroll 4
            for (int k = 0; k < H2D; ++k) a += st[r][k] * W3s[k * NCLS + c];
            ((__half*)g_A)[(size_t)grow * NCLS + c] = __float2half(a);
        }
    }
}

// ---------------- spmm3 (half gather) + tanh + softmax (R9, passing) -------

__global__ __launch_bounds__(256) void spmm3_softmax_kernel(float* __restrict__ out, int n)
{
    int row = blockIdx.x * blockDim.x + threadIdx.x;
    if (row >= n) return;
    const uint4* Hh = (const uint4*)g_A;

    float acc[NCLS];
    #pragma unroll
    for (int j = 0; j < NCLS; j++) acc[j] = 0.f;

    int s = g_rowptr[row], e = g_rowptr[row + 1];
    for (int j = s; j < e; ++j) {
        int   c  = __ldg(&g_colidx[j]);
        float wj = __ldg(&g_wnorm[j]);
        uint4 v0 = Hh[(size_t)c * 2];
        uint4 v1 = Hh[(size_t)c * 2 + 1];
        #pragma unroll
        for (int q = 0; q < 4; ++q) {
            float2 f = __half22float2(*(const __half2*)((&v0.x) + q));
            acc[2 * q] += wj * f.x; acc[2 * q + 1] += wj * f.y;
        }
        #pragma unroll
        for (int q = 0; q < 4; ++q) {
            float2 f = __half22float2(*(const __half2*)((&v1.x) + q));
            acc[8 + 2 * q] += wj * f.x; acc[8 + 2 * q + 1] += wj * f.y;
        }
    }
    float mx = -1e30f;
    #pragma unroll
    for (int j = 0; j < NCLS; j++) { acc[j] = tanhf(acc[j]); mx = fmaxf(mx, acc[j]); }
    float sum = 0.f;
    #pragma unroll
    for (int j = 0; j < NCLS; j++) { acc[j] = expf(acc[j] - mx); sum += acc[j]; }
    float inv = 1.f / sum;
    float* o = out + (size_t)row * NCLS;
    #pragma unroll
    for (int j = 0; j < NCLS; j++) o[j] = acc[j] * inv;
}

// ---------------- launch ----------------

extern "C" void kernel_launch(void* const* d_in, const int* in_sizes, int n_in,
                              void* d_out, int out_size)
{
    const float* x  = (const float*)d_in[0];
    const void*  ei = d_in[1];
    const float* W1 = (const float*)d_in[2];
    const float* b1 = (const float*)d_in[3];
    const float* W2 = (const float*)d_in[4];
    const float* b2 = (const float*)d_in[5];
    const float* W3 = (const float*)d_in[6];
    const float* b3 = (const float*)d_in[7];
    float* out = (float*)d_out;

    int n = in_sizes[0] / F_IN;   // 50000
    int E = in_sizes[1] / 2;      // 800000

    cudaStream_t s2;
    cudaStreamCreateWithFlags(&s2, cudaStreamNonBlocking);
    cudaEvent_t evFork, evJoin;
    cudaEventCreateWithFlags(&evFork, cudaEventDisableTiming);
    cudaEventCreateWithFlags(&evJoin, cudaEventDisableTiming);

    cudaEventRecord(evFork, 0);
    cudaStreamWaitEvent(s2, evFork, 0);

    // enqueue order keeps gemm1 at launch index 3 (ncu -s 5 -c 1 lands there)
    detect_init_kernel<<<1 + (n + 255) / 256, 256, 0, s2>>>((const long long*)ei, n); // 0
    conv_x_kernel<<<(n * 256 + 255) / 256, 256>>>(x, n);                              // 1 (main)
    conv_w_kernel<<<1024, 256>>>(W1, W2);                                             // 2 (main)
    {   // layer-1 GEMM: g_X (half) x Wt1 (half) -> g_H half (pitch 256 half2)        // 3 (main)
        dim3 g((H1D + BN - 1) / BN, (n + BM - 1) / BM);
        gemm_mma_kernel<<<g, 256>>>(nullptr, 3, 512, 1, nullptr, 0, b1,
                                    256, n, H1D, F_IN);
    }
    hist_kernel<<<(E + 255) / 256, 256, 0, s2>>>(ei, E);                              // 4
    scan_p1_kernel<<<NB_SCAN, 256, 0, s2>>>(n);                                       // 5
    scan_p2_kernel<<<1, 256, 0, s2>>>();                                              // 6
    scan_p3_kernel<<<NB_SCAN, 256, 0, s2>>>(n);                                       // 7
    fill_kernel<<<(E + n + 255) / 256, 256, 0, s2>>>(ei, E, n);                       // 8
    cudaEventRecord(evJoin, s2);

    // join: SpMM1 needs both CSR and GEMM1
    cudaStreamWaitEvent(0, evJoin, 0);
    spmm1_tanh_h_kernel<<<(n * 64 + 255) / 256, 256>>>(n);

    // layer-2 GEMM: g_A (half) x Wt2 (half, zero-padded k>=500) -> g_H half
    {
        dim3 g((H2D + BN - 1) / BN, (n + BM - 1) / BM);
        gemm_mma_kernel<<<g, 256>>>(nullptr, 1, 512, 2, nullptr, 0, b2,
                                    64, n, H2D, H1D);
    }

    // fused SpMM2 + tanh + gemm3 -> g_A half (pitch 16), then spmm3+softmax
    spmm2_gemm3_kernel<<<(n + 7) / 8, 256>>>(W3, b3, n);
    spmm3_softmax_kernel<<<(n + 255) / 256, 256>>>(out, n);

    cudaEventDestroy(evFork);
    cudaEventDestroy(evJoin);
    cudaStreamDestroy(s2);
}